// round 15
// baseline (speedup 1.0000x reference)
#include <cuda_runtime.h>
#include <cuda_bf16.h>
#include <cuda_fp16.h>
#include <cstdint>

// Problem constants
#define DIMK   512
#define NCODE  8192
#define NTOK   16384           // B*N = 4*4096
#define QELEMS (NTOK * DIMK)   // 8388608

#define MARGIN   0.09f          // worst-case fp16 score error ~0.047; 2x safety
#define SEGCAP   16
#define NSEG     32             // per token: 32 segments x 16 entries

// ---------------- scratch (no allocations allowed) ----------------
__device__ float   g_implicit[(size_t)NCODE * DIMK];    // 16 MB fp32 (exact)
__device__ __half  g_implicit_h[(size_t)NCODE * DIMK];  // 8 MB fp16 (for HMMA)
__device__ __half  g_cbh[(size_t)NCODE * DIMK];         // codebook hi
__device__ __half  g_cbl[(size_t)NCODE * DIMK];         // codebook lo
__device__ __half  g_wh[(size_t)DIMK * DIMK];           // W hi
__device__ __half  g_wl[(size_t)DIMK * DIMK];           // W lo
__device__ float   g_cnorm[NCODE];
__device__ float   g_partial[NTOK];
__device__ int     g_cand[(size_t)NTOK * NSEG * SEGCAP];  // 32 MB
__device__ int     g_candcnt[(size_t)NTOK * NSEG];        // 2 MB

// ===================== helpers =====================
__device__ __forceinline__ uint32_t smem_to_u32(const void* p) {
    uint32_t a;
    asm("{ .reg .u64 t; cvta.to.shared.u64 t, %1; cvt.u32.u64 %0, t; }" : "=r"(a) : "l"(p));
    return a;
}
// L2-direct bulk copy (validated R9: .ca's L1 fill thrashes the small L1 slice)
#define CP_ASYNC16(dst, src) \
    asm volatile("cp.async.cg.shared.global [%0], [%1], 16;" :: "r"(dst), "l"(src))
#define CP_COMMIT() asm volatile("cp.async.commit_group;")
#define CP_WAIT(n)  asm volatile("cp.async.wait_group %0;" :: "n"(n))

__device__ __forceinline__ void ldsm_x4(uint32_t r[4], uint32_t addr) {
    asm volatile("ldmatrix.sync.aligned.m8n8.x4.shared.b16 {%0,%1,%2,%3}, [%4];"
                 : "=r"(r[0]), "=r"(r[1]), "=r"(r[2]), "=r"(r[3]) : "r"(addr));
}
__device__ __forceinline__ void ldsm_x2(uint32_t r[2], uint32_t addr) {
    asm volatile("ldmatrix.sync.aligned.m8n8.x2.shared.b16 {%0,%1}, [%2];"
                 : "=r"(r[0]), "=r"(r[1]) : "r"(addr));
}
__device__ __forceinline__ void mma_fp16(float d[4], const uint32_t a[4], const uint32_t b[2]) {
    asm volatile("mma.sync.aligned.m16n8k16.row.col.f32.f16.f16.f32 "
                 "{%0,%1,%2,%3}, {%4,%5,%6,%7}, {%8,%9}, {%0,%1,%2,%3};"
                 : "+f"(d[0]), "+f"(d[1]), "+f"(d[2]), "+f"(d[3])
                 : "r"(a[0]), "r"(a[1]), "r"(a[2]), "r"(a[3]), "r"(b[0]), "r"(b[1]));
}

// =====================================================================
// Kernel 0: hi/lo fp16 split of codebook and W.
// =====================================================================
#define CB_F4 ((NCODE * DIMK) / 4)   // 1048576
#define W_F4  ((DIMK * DIMK) / 4)    // 65536
__global__ __launch_bounds__(256)
void split_kernel(const float* __restrict__ CB, const float* __restrict__ W) {
    const int idx = blockIdx.x * 256 + threadIdx.x;
    const float4* src;
    __half2 *dh, *dl;
    int i = idx;
    if (idx < CB_F4) {
        src = (const float4*)CB; dh = (__half2*)g_cbh; dl = (__half2*)g_cbl;
    } else {
        i = idx - CB_F4;
        if (i >= W_F4) return;
        src = (const float4*)W; dh = (__half2*)g_wh; dl = (__half2*)g_wl;
    }
    float4 v = src[i];
    __half hx = __float2half_rn(v.x), hy = __float2half_rn(v.y);
    __half hz = __float2half_rn(v.z), hw = __float2half_rn(v.w);
    __half lx = __float2half_rn(v.x - __half2float(hx));
    __half ly = __float2half_rn(v.y - __half2float(hy));
    __half lz = __float2half_rn(v.z - __half2float(hz));
    __half lw = __float2half_rn(v.w - __half2float(hw));
    dh[i * 2]     = __halves2half2(hx, hy);
    dh[i * 2 + 1] = __halves2half2(hz, hw);
    dl[i * 2]     = __halves2half2(lx, ly);
    dl[i * 2 + 1] = __halves2half2(lz, lw);
}

// =====================================================================
// Kernel 1: implicit[c,d] via split-fp16 HMMA (R10-proven, unchanged).
// =====================================================================
#define IROW  144
#define IMAT  (128 * IROW)            // 18432
#define IBUF  (4 * IMAT)              // Ah, Al, Bh, Bl
#define ISM_TOTAL (2 * IBUF)          // 147456

__global__ __launch_bounds__(256, 1)
void implicit_split_kernel() {
    extern __shared__ char smem[];
    const uint32_t sbase = smem_to_u32(smem);
    const int tid = threadIdx.x, lane = tid & 31, wid = tid >> 5;
    const int warp_m = wid & 1, warp_n = wid >> 1;
    const int rowA0 = blockIdx.x * 128;   // codes
    const int rowB0 = blockIdx.y * 128;   // d-cols

    const int brow = tid >> 1;
    const int bcol = (tid & 1) * 64;      // bytes

    auto issue_chunk = [&](int kc, int bu) {
        const size_t offA = ((size_t)(rowA0 + brow) * DIMK + kc * 64) * 2 + bcol;
        const size_t offB = ((size_t)(rowB0 + brow) * DIMK + kc * 64) * 2 + bcol;
        const uint32_t d0 = sbase + bu * IBUF + brow * IROW + bcol;
        const char* sa_h = (const char*)g_cbh + offA;
        const char* sa_l = (const char*)g_cbl + offA;
        const char* sb_h = (const char*)g_wh + offB;
        const char* sb_l = (const char*)g_wl + offB;
#pragma unroll
        for (int i = 0; i < 4; i++) {
            CP_ASYNC16(d0 + 0 * IMAT + i * 16, sa_h + i * 16);
            CP_ASYNC16(d0 + 1 * IMAT + i * 16, sa_l + i * 16);
            CP_ASYNC16(d0 + 2 * IMAT + i * 16, sb_h + i * 16);
            CP_ASYNC16(d0 + 3 * IMAT + i * 16, sb_l + i * 16);
        }
        CP_COMMIT();
    };

    float acc[4][4][4];
#pragma unroll
    for (int mi = 0; mi < 4; mi++)
#pragma unroll
        for (int ni = 0; ni < 4; ni++)
#pragma unroll
            for (int r = 0; r < 4; r++) acc[mi][ni][r] = 0.f;

    issue_chunk(0, 0);

    for (int kc = 0; kc < 8; kc++) {
        CP_WAIT(0);
        __syncthreads();
        if (kc + 1 < 8) issue_chunk(kc + 1, (kc + 1) & 1);

        const uint32_t base = sbase + (kc & 1) * IBUF;
#pragma unroll
        for (int kk = 0; kk < 4; kk++) {
            uint32_t ah[4][4], al[4][4], bb[4][2];
            const uint32_t akoff = kk * 32 + (lane >> 4) * 16;
            const uint32_t bkoff = kk * 32 + ((lane >> 3) & 1) * 16;
#pragma unroll
            for (int mi = 0; mi < 4; mi++) {
                uint32_t ar = (warp_m * 64 + mi * 16 + (lane & 15)) * IROW + akoff;
                ldsm_x4(ah[mi], base + 0 * IMAT + ar);
                ldsm_x4(al[mi], base + 1 * IMAT + ar);
            }
#pragma unroll
            for (int ni = 0; ni < 4; ni++) {
                uint32_t br = (warp_n * 32 + ni * 8 + (lane & 7)) * IROW + bkoff;
                ldsm_x2(bb[ni], base + 2 * IMAT + br);   // Bh
            }
#pragma unroll
            for (int mi = 0; mi < 4; mi++)
#pragma unroll
                for (int ni = 0; ni < 4; ni++) {
                    mma_fp16(acc[mi][ni], ah[mi], bb[ni]);   // Ah*Bh
                    mma_fp16(acc[mi][ni], al[mi], bb[ni]);   // Al*Bh
                }
#pragma unroll
            for (int ni = 0; ni < 4; ni++) {
                uint32_t br = (warp_n * 32 + ni * 8 + (lane & 7)) * IROW + bkoff;
                ldsm_x2(bb[ni], base + 3 * IMAT + br);   // Bl
            }
#pragma unroll
            for (int mi = 0; mi < 4; mi++)
#pragma unroll
                for (int ni = 0; ni < 4; ni++)
                    mma_fp16(acc[mi][ni], ah[mi], bb[ni]);   // Ah*Bl
        }
    }

#pragma unroll
    for (int mi = 0; mi < 4; mi++)
#pragma unroll
        for (int half = 0; half < 2; half++) {
            const int r = rowA0 + warp_m * 64 + mi * 16 + (lane >> 2) + half * 8;
#pragma unroll
            for (int ni = 0; ni < 4; ni++) {
                const int c = rowB0 + warp_n * 32 + ni * 8 + (lane & 3) * 2;
                float2 v = make_float2(acc[mi][ni][half * 2], acc[mi][ni][half * 2 + 1]);
                *(float2*)&g_implicit[(size_t)r * DIMK + c] = v;
                __half2 h;
                h.x = __float2half_rn(v.x);
                h.y = __float2half_rn(v.y);
                *(__half2*)&g_implicit_h[(size_t)r * DIMK + c] = h;
            }
        }
}

// =====================================================================
// Kernel 1b: c_norm[c] = ||implicit[c]||^2
// =====================================================================
__global__ void cnorm_kernel() {
    int c = blockIdx.x * 8 + (threadIdx.x >> 5);
    int lane = threadIdx.x & 31;
    const float* p = g_implicit + (size_t)c * DIMK;
    float s = 0.f;
#pragma unroll
    for (int j = 0; j < DIMK / 32; j++) {
        float v = p[lane + j * 32];
        s = fmaf(v, v, s);
    }
#pragma unroll
    for (int o = 16; o; o >>= 1) s += __shfl_xor_sync(0xffffffffu, s, o);
    if (lane == 0) g_cnorm[c] = s;
}

// =====================================================================
// Kernel 2: fp16 HMMA score GEMM + candidate collection.
// R15: warp tile 64x32 (10.7 MAC/ldsm-byte vs 8 for 32x32) to cut SMEM
// crossbar traffic 25% (identified as co-binder with HMMA). CTA covers
// 128 tokens x 256-code tiles; 16 warps as 2(M) x 8(N). k-chunk 32 so
// the B chunk stays 16KB -> R13-proven 3-ring @ distance 2 pipeline.
// 512 iterations (it -> ct = it>>4, kc = it&15), epilogue at kc==15.
// BROW=80: ldsm row starts hit banks {0,20,8,28,16,4,24,12} - no
// conflicts. cnorm in SMEM. grid = 128 CTAs, 1 CTA/SM.
// =====================================================================
#define NBUF  3
#define BROW  80                      // 64 B data + 16 pad (conflict-free)
#define BBUF  (256 * BROW)            // 20480
#define SM_CN 0                       // 8192 floats = 32768 B
#define SM_A  32768                   // 128 rows x 1040 B = 133120 B
#define SM_B  (32768 + 133120)        // 165888
#define SM_TOTAL (SM_B + NBUF * BBUF) // 227328 B
#define AROW 1040

__global__ __launch_bounds__(512, 1)
void mma_argmin_kernel(const float* __restrict__ X) {
    extern __shared__ char smem[];
    const uint32_t sbase = smem_to_u32(smem);
    const int tid = threadIdx.x, lane = tid & 31, wid = tid >> 5;
    const int warp_m = wid & 1, warp_n = wid >> 1;   // 2 x 8
    const int row0 = blockIdx.x * 128;

    // B loader geometry: 2 threads/row, 32B each (row = 64 B data)
    const int brow = tid >> 1;
    const int bcol = (tid & 1) * 32;

    // prologue: issue chunks 0 and 1 (fly during cnorm/A-convert)
    {
        const char* g0 = (const char*)g_implicit_h + ((size_t)brow * DIMK) * 2 + bcol;
        uint32_t d0 = sbase + SM_B + brow * BROW + bcol;
        CP_ASYNC16(d0, g0);
        CP_ASYNC16(d0 + 16, g0 + 16);
        CP_COMMIT();
        const char* g1 = (const char*)g_implicit_h + ((size_t)brow * DIMK + 32) * 2 + bcol;
        uint32_t d1 = sbase + SM_B + BBUF + brow * BROW + bcol;
        CP_ASYNC16(d1, g1);
        CP_ASYNC16(d1 + 16, g1 + 16);
        CP_COMMIT();
    }

    // cnorm -> SMEM (2048 float4, 512 threads x 4)
#pragma unroll
    for (int j = 0; j < 4; j++)
        ((float4*)smem)[tid + j * 512] = ((const float4*)g_cnorm)[tid + j * 512];

    // A-tile: convert 128 token rows fp32 -> fp16 into SMEM (4 thr/row)
    {
        const int r = tid >> 2, q = tid & 3;
        const float4* xr = (const float4*)(X + (size_t)(row0 + r) * DIMK) + q * 32;
        char* arow = smem + SM_A + r * AROW + q * 256;
#pragma unroll
        for (int j = 0; j < 16; j++) {
            float4 v0 = xr[2 * j], v1 = xr[2 * j + 1];
            __half2 h0, h1, h2, h3;
            h0.x = __float2half_rn(v0.x); h0.y = __float2half_rn(v0.y);
            h1.x = __float2half_rn(v0.z); h1.y = __float2half_rn(v0.w);
            h2.x = __float2half_rn(v1.x); h2.y = __float2half_rn(v1.y);
            h3.x = __float2half_rn(v1.z); h3.y = __float2half_rn(v1.w);
            uint4 pk;
            pk.x = *(uint32_t*)&h0; pk.y = *(uint32_t*)&h1;
            pk.z = *(uint32_t*)&h2; pk.w = *(uint32_t*)&h3;
            *(uint4*)(arow + j * 16) = pk;
        }
    }

    float acc[4][4][4];
#pragma unroll
    for (int mi = 0; mi < 4; mi++)
#pragma unroll
        for (int ni = 0; ni < 4; ni++)
#pragma unroll
            for (int r = 0; r < 4; r++) acc[mi][ni][r] = 0.f;

    float R[8]; int cnt[8];
#pragma unroll
    for (int s = 0; s < 8; s++) { R[s] = 3.4e38f; cnt[s] = 0; }

    int buf = 0;           // buffer holding chunk `it`
    // 512 iterations: it -> (ct = it>>4 code tile of 256, kc = it&15 k-chunk of 32)
    for (int it = 0; it < 512; it++) {
        // groups retire in commit order: <=1 outstanding => chunk `it` landed
        if (it == 511) { CP_WAIT(0); } else { CP_WAIT(1); }
        __syncthreads();   // all warps done with buf[(it+2)%3]'s previous chunk

        if (it + 2 < 512) {  // prefetch chunk it+2: two iterations of slack
            const int nc = it + 2;
            const int nct = nc >> 4, nkc = nc & 15;
            const char* g = (const char*)g_implicit_h
                + ((size_t)(nct * 256 + brow) * DIMK + nkc * 32) * 2 + bcol;
            int nbuf = buf + 2; if (nbuf >= NBUF) nbuf -= NBUF;
            uint32_t d = sbase + SM_B + nbuf * BBUF + brow * BROW + bcol;
            CP_ASYNC16(d, g);
            CP_ASYNC16(d + 16, g + 16);
            CP_COMMIT();
        }

        const uint32_t b0 = sbase + SM_B + buf * BBUF;
        const int kc = it & 15;
#pragma unroll
        for (int kk = 0; kk < 2; kk++) {
            uint32_t a[4][4], b[4][2];
#pragma unroll
            for (int mi = 0; mi < 4; mi++) {
                uint32_t addr = sbase + SM_A
                    + (warp_m * 64 + mi * 16 + (lane & 15)) * AROW
                    + (kc * 32 + kk * 16 + (lane >> 4) * 8) * 2;
                ldsm_x4(a[mi], addr);
            }
#pragma unroll
            for (int ni = 0; ni < 4; ni++) {
                uint32_t addr = b0 + (warp_n * 32 + ni * 8 + (lane & 7)) * BROW
                    + (kk * 16 + ((lane >> 3) & 1) * 8) * 2;
                ldsm_x2(b[ni], addr);
            }
#pragma unroll
            for (int mi = 0; mi < 4; mi++)
#pragma unroll
                for (int ni = 0; ni < 4; ni++)
                    mma_fp16(acc[mi][ni], a[mi], b[ni]);
        }

        if (kc == 15) {
            const int ct = it >> 4;
#pragma unroll
            for (int mi = 0; mi < 4; mi++) {
#pragma unroll
                for (int half = 0; half < 2; half++) {
                    const int slot = mi * 2 + half;
                    float sv[8]; int cv[8];
#pragma unroll
                    for (int ni = 0; ni < 4; ni++) {
#pragma unroll
                        for (int rr = 0; rr < 2; rr++) {
                            int c = ct * 256 + warp_n * 32 + ni * 8 + (lane & 3) * 2 + rr;
                            float cn = *(const float*)(smem + 4 * c);
                            float s = fmaf(-2.f, acc[mi][ni][half * 2 + rr], cn);
                            sv[ni * 2 + rr] = s; cv[ni * 2 + rr] = c;
                            acc[mi][ni][half * 2 + rr] = 0.f;
                        }
                    }
                    float t = sv[0];
#pragma unroll
                    for (int j = 1; j < 8; j++) t = fminf(t, sv[j]);
                    t = fminf(t, __shfl_xor_sync(0xffffffffu, t, 1));
                    t = fminf(t, __shfl_xor_sync(0xffffffffu, t, 2));
                    R[slot] = fminf(R[slot], t);
                    const float thr = R[slot] + MARGIN;
                    if (t < thr) {
                        const int tok = row0 + warp_m * 64 + mi * 16 + (lane >> 2) + half * 8;
                        int* seg_base = g_cand + (size_t)tok * (NSEG * SEGCAP)
                                        + (warp_n * 4 + (lane & 3)) * SEGCAP;
#pragma unroll
                        for (int j = 0; j < 8; j++) {
                            if (sv[j] < thr) {
                                if (cnt[slot] < SEGCAP) seg_base[cnt[slot]] = cv[j];
                                cnt[slot]++;
                            }
                        }
                    }
                }
            }
        }
        buf++; if (buf == NBUF) buf = 0;
    }

#pragma unroll
    for (int mi = 0; mi < 4; mi++)
#pragma unroll
        for (int half = 0; half < 2; half++) {
            const int slot = mi * 2 + half;
            const int tok = row0 + warp_m * 64 + mi * 16 + (lane >> 2) + half * 8;
            const int seg = warp_n * 4 + (lane & 3);
            g_candcnt[(size_t)tok * NSEG + seg] = cnt[slot];
        }
}

// =====================================================================
// Kernel 2b: exact fp32 rescore, 2 warps/token; each warp owns 16 of
// the 32 segments. Merge via SMEM with index tie-break; fused gather.
// =====================================================================
__global__ __launch_bounds__(256)
void rescue_kernel(const float* __restrict__ X, float* __restrict__ out,
                   int write_idx) {
    __shared__ float sbv[8];
    __shared__ int   sbi[8];
    __shared__ int   sovf[8];
    const int w = threadIdx.x >> 5, lane = threadIdx.x & 31;
    const int pair = w >> 1, half = w & 1;
    const int t = blockIdx.x * 4 + pair;

    const float4* xr = (const float4*)(X + (size_t)t * DIMK) + lane * 4;
    const float4 x0 = xr[0], x1 = xr[1], x2 = xr[2], x3 = xr[3];

    int cnts[16]; bool myovf = false;
#pragma unroll
    for (int s = 0; s < 16; s++) {
        int c = g_candcnt[(size_t)t * NSEG + half * 16 + s];
        cnts[s] = c;
        if (c > SEGCAP) myovf = true;
    }
    if (lane == 0) sovf[w] = myovf ? 1 : 0;
    __syncthreads();
    const bool ovf = (sovf[pair * 2] | sovf[pair * 2 + 1]) != 0;

    float bv = 3.4e38f; int bi = 0x7fffffff;

    auto score = [&](int c) {
        const float4* cr = (const float4*)(g_implicit + (size_t)c * DIMK) + lane * 4;
        float4 c0 = cr[0], c1 = cr[1], c2 = cr[2], c3 = cr[3];
        float acc = 0.f;
        acc = fmaf(x0.x, c0.x, acc); acc = fmaf(x0.y, c0.y, acc);
        acc = fmaf(x0.z, c0.z, acc); acc = fmaf(x0.w, c0.w, acc);
        acc = fmaf(x1.x, c1.x, acc); acc = fmaf(x1.y, c1.y, acc);
        acc = fmaf(x1.z, c1.z, acc); acc = fmaf(x1.w, c1.w, acc);
        acc = fmaf(x2.x, c2.x, acc); acc = fmaf(x2.y, c2.y, acc);
        acc = fmaf(x2.z, c2.z, acc); acc = fmaf(x2.w, c2.w, acc);
        acc = fmaf(x3.x, c3.x, acc); acc = fmaf(x3.y, c3.y, acc);
        acc = fmaf(x3.z, c3.z, acc); acc = fmaf(x3.w, c3.w, acc);
#pragma unroll
        for (int o = 16; o; o >>= 1) acc += __shfl_xor_sync(0xffffffffu, acc, o);
        float s = fmaf(-2.0f, acc, __ldg(&g_cnorm[c]));
        if (s < bv || (s == bv && c < bi)) { bv = s; bi = c; }
    };

    if (ovf) {
        for (int c = half * (NCODE / 2); c < (half + 1) * (NCODE / 2); c++) score(c);
    } else {
#pragma unroll 1
        for (int s = 0; s < 16; s++) {
            const int* seg = g_cand + (size_t)t * (NSEG * SEGCAP)
                             + (half * 16 + s) * SEGCAP;
            for (int j = 0; j < cnts[s]; j++) score(seg[j]);
        }
    }

    if (lane == 0) { sbv[w] = bv; sbi[w] = bi; }
    __syncthreads();

    if (half == 0) {
        float bv2 = sbv[w + 1]; int bi2 = sbi[w + 1];
        if (bv2 < bv || (bv2 == bv && bi2 < bi)) { bv = bv2; bi = bi2; }

        const float4* qr = (const float4*)(g_implicit + (size_t)bi * DIMK) + lane * 4;
        const float4 q0 = qr[0], q1 = qr[1], q2 = qr[2], q3 = qr[3];
        float4* orow = (float4*)out + (size_t)t * (DIMK / 4) + lane * 4;
        orow[0] = q0; orow[1] = q1; orow[2] = q2; orow[3] = q3;

        float s =
            (x0.x - q0.x) * (x0.x - q0.x) + (x0.y - q0.y) * (x0.y - q0.y) +
            (x0.z - q0.z) * (x0.z - q0.z) + (x0.w - q0.w) * (x0.w - q0.w) +
            (x1.x - q1.x) * (x1.x - q1.x) + (x1.y - q1.y) * (x1.y - q1.y) +
            (x1.z - q1.z) * (x1.z - q1.z) + (x1.w - q1.w) * (x1.w - q1.w) +
            (x2.x - q2.x) * (x2.x - q2.x) + (x2.y - q2.y) * (x2.y - q2.y) +
            (x2.z - q2.z) * (x2.z - q2.z) + (x2.w - q2.w) * (x2.w - q2.w) +
            (x3.x - q3.x) * (x3.x - q3.x) + (x3.y - q3.y) * (x3.y - q3.y) +
            (x3.z - q3.z) * (x3.z - q3.z) + (x3.w - q3.w) * (x3.w - q3.w);
#pragma unroll
        for (int o = 16; o; o >>= 1) s += __shfl_xor_sync(0xffffffffu, s, o);
        if (lane == 0) {
            g_partial[t] = s;
            if (write_idx) out[(size_t)QELEMS + t] = (float)bi;
        }
    }
}

// =====================================================================
// Kernel 4: deterministic loss reduction (fp64 accumulate).
// =====================================================================
__global__ void loss_kernel(float* __restrict__ out_loss) {
    __shared__ double sh[256];
    double s = 0.0;
    for (int i = threadIdx.x; i < NTOK; i += 256) s += (double)g_partial[i];
    sh[threadIdx.x] = s;
    __syncthreads();
    for (int o = 128; o; o >>= 1) {
        if (threadIdx.x < o) sh[threadIdx.x] += sh[threadIdx.x + o];
        __syncthreads();
    }
    if (threadIdx.x == 0)
        *out_loss = (float)(1.25 * sh[0] / (double)QELEMS);
}

// =====================================================================
extern "C" void kernel_launch(void* const* d_in, const int* in_sizes, int n_in,
                              void* d_out, int out_size) {
    const float* x = nullptr; const float* cb = nullptr; const float* W = nullptr;
    for (int i = 0; i < n_in; i++) {
        if (in_sizes[i] == NTOK * DIMK)       x  = (const float*)d_in[i];
        else if (in_sizes[i] == NCODE * DIMK) cb = (const float*)d_in[i];
        else if (in_sizes[i] == DIMK * DIMK)  W  = (const float*)d_in[i];
    }
    float* out = (float*)d_out;

    split_kernel<<<(CB_F4 + W_F4 + 255) / 256, 256>>>(cb, W);

    cudaFuncSetAttribute(implicit_split_kernel,
                         cudaFuncAttributeMaxDynamicSharedMemorySize, ISM_TOTAL);
    implicit_split_kernel<<<dim3(NCODE / 128, DIMK / 128), 256, ISM_TOTAL>>>();

    cnorm_kernel<<<NCODE / 8, 256>>>();

    cudaFuncSetAttribute(mma_argmin_kernel,
                         cudaFuncAttributeMaxDynamicSharedMemorySize, SM_TOTAL);
    mma_argmin_kernel<<<NTOK / 128, 512, SM_TOTAL>>>(x);

    const int write_idx = (out_size >= QELEMS + NTOK) ? 1 : 0;
    rescue_kernel<<<NTOK / 4, 256>>>(x, out, write_idx);

    if (out_size >= QELEMS + NTOK + 1)
        loss_kernel<<<1, 256>>>(out + (size_t)QELEMS + NTOK);
}

// round 16
// speedup vs baseline: 1.0595x; 1.0595x over previous
#include <cuda_runtime.h>
#include <cuda_bf16.h>
#include <cuda_fp16.h>
#include <cstdint>

// Problem constants
#define DIMK   512
#define NCODE  8192
#define NTOK   16384           // B*N = 4*4096
#define QELEMS (NTOK * DIMK)   // 8388608

#define MARGIN   0.09f          // worst-case fp16 score error ~0.047; 2x safety
#define SEGCAP   16
#define NSEG     16             // per token: 16 segments x 16 entries

// ---------------- scratch (no allocations allowed) ----------------
__device__ float   g_implicit[(size_t)NCODE * DIMK];    // 16 MB fp32 (exact)
__device__ __half  g_implicit_h[(size_t)NCODE * DIMK];  // 8 MB fp16 (for HMMA)
__device__ __half  g_cbh[(size_t)NCODE * DIMK];         // codebook hi
__device__ __half  g_cbl[(size_t)NCODE * DIMK];         // codebook lo
__device__ __half  g_wh[(size_t)DIMK * DIMK];           // W hi
__device__ __half  g_wl[(size_t)DIMK * DIMK];           // W lo
__device__ float   g_cnorm[NCODE];
__device__ float   g_partial[NTOK];
__device__ int     g_cand[(size_t)NTOK * NSEG * SEGCAP];  // 16 MB
__device__ int     g_candcnt[(size_t)NTOK * NSEG];        // 1 MB

// ===================== helpers =====================
__device__ __forceinline__ uint32_t smem_to_u32(const void* p) {
    uint32_t a;
    asm("{ .reg .u64 t; cvta.to.shared.u64 t, %1; cvt.u32.u64 %0, t; }" : "=r"(a) : "l"(p));
    return a;
}
// L2-direct bulk copy (validated R9: .ca's L1 fill thrashes the small L1 slice)
#define CP_ASYNC16(dst, src) \
    asm volatile("cp.async.cg.shared.global [%0], [%1], 16;" :: "r"(dst), "l"(src))
#define CP_COMMIT() asm volatile("cp.async.commit_group;")
#define CP_WAIT(n)  asm volatile("cp.async.wait_group %0;" :: "n"(n))

__device__ __forceinline__ void ldsm_x4(uint32_t r[4], uint32_t addr) {
    asm volatile("ldmatrix.sync.aligned.m8n8.x4.shared.b16 {%0,%1,%2,%3}, [%4];"
                 : "=r"(r[0]), "=r"(r[1]), "=r"(r[2]), "=r"(r[3]) : "r"(addr));
}
__device__ __forceinline__ void ldsm_x2(uint32_t r[2], uint32_t addr) {
    asm volatile("ldmatrix.sync.aligned.m8n8.x2.shared.b16 {%0,%1}, [%2];"
                 : "=r"(r[0]), "=r"(r[1]) : "r"(addr));
}
__device__ __forceinline__ void mma_fp16(float d[4], const uint32_t a[4], const uint32_t b[2]) {
    asm volatile("mma.sync.aligned.m16n8k16.row.col.f32.f16.f16.f32 "
                 "{%0,%1,%2,%3}, {%4,%5,%6,%7}, {%8,%9}, {%0,%1,%2,%3};"
                 : "+f"(d[0]), "+f"(d[1]), "+f"(d[2]), "+f"(d[3])
                 : "r"(a[0]), "r"(a[1]), "r"(a[2]), "r"(a[3]), "r"(b[0]), "r"(b[1]));
}

// =====================================================================
// Kernel 0: hi/lo fp16 split of codebook and W.
// =====================================================================
#define CB_F4 ((NCODE * DIMK) / 4)   // 1048576
#define W_F4  ((DIMK * DIMK) / 4)    // 65536
__global__ __launch_bounds__(256)
void split_kernel(const float* __restrict__ CB, const float* __restrict__ W) {
    const int idx = blockIdx.x * 256 + threadIdx.x;
    const float4* src;
    __half2 *dh, *dl;
    int i = idx;
    if (idx < CB_F4) {
        src = (const float4*)CB; dh = (__half2*)g_cbh; dl = (__half2*)g_cbl;
    } else {
        i = idx - CB_F4;
        if (i >= W_F4) return;
        src = (const float4*)W; dh = (__half2*)g_wh; dl = (__half2*)g_wl;
    }
    float4 v = src[i];
    __half hx = __float2half_rn(v.x), hy = __float2half_rn(v.y);
    __half hz = __float2half_rn(v.z), hw = __float2half_rn(v.w);
    __half lx = __float2half_rn(v.x - __half2float(hx));
    __half ly = __float2half_rn(v.y - __half2float(hy));
    __half lz = __float2half_rn(v.z - __half2float(hz));
    __half lw = __float2half_rn(v.w - __half2float(hw));
    dh[i * 2]     = __halves2half2(hx, hy);
    dh[i * 2 + 1] = __halves2half2(hz, hw);
    dl[i * 2]     = __halves2half2(lx, ly);
    dl[i * 2 + 1] = __halves2half2(lz, lw);
}

// =====================================================================
// Kernel 1: implicit[c,d] via split-fp16 HMMA.
// R16: 512 threads (16 warps, 4Mx4N, warp tile 32x32) + ring-3 @ d2
// cp.async pipeline — the structure proven on the mma_argmin kernel.
// D = Ah*Bh + Al*Bh + Ah*Bl (fp32 accum; Al*Bl dropped ~2^-22 rel).
// Per chunk: Ah/Al (codes) + Bh/Bl (W cols), 128 rows x 64k each.
// SMEM = 3 x 73728 = 221184. grid (NCODE/128, DIMK/128) = 256 CTAs.
// =====================================================================
#define IROW  144
#define IMAT  (128 * IROW)            // 18432
#define IBUF  (4 * IMAT)              // Ah, Al, Bh, Bl
#define ISM_TOTAL (3 * IBUF)          // 221184

__global__ __launch_bounds__(512, 1)
void implicit_split_kernel() {
    extern __shared__ char smem[];
    const uint32_t sbase = smem_to_u32(smem);
    const int tid = threadIdx.x, lane = tid & 31, wid = tid >> 5;
    const int warp_m = wid & 3, warp_n = wid >> 2;   // 4 x 4
    const int rowA0 = blockIdx.x * 128;   // codes
    const int rowB0 = blockIdx.y * 128;   // d-cols

    // loader: threads 0-127 Ah, 128-255 Al, 256-383 Bh, 384-511 Bl
    const int lrow = tid & 127;
    const int lsel = tid >> 7;
    const __half* lsrc = (lsel == 0) ? g_cbh : (lsel == 1) ? g_cbl
                        : (lsel == 2) ? g_wh : g_wl;
    const int lbase = (lsel < 2) ? rowA0 : rowB0;

    auto issue_chunk = [&](int kc, int bu) {
        const char* g = (const char*)(lsrc + (size_t)(lbase + lrow) * DIMK + kc * 64);
        const uint32_t d = sbase + bu * IBUF + lsel * IMAT + lrow * IROW;
#pragma unroll
        for (int i = 0; i < 8; i++) CP_ASYNC16(d + i * 16, g + i * 16);
        CP_COMMIT();
    };

    float acc[2][4][4];
#pragma unroll
    for (int mi = 0; mi < 2; mi++)
#pragma unroll
        for (int ni = 0; ni < 4; ni++)
#pragma unroll
            for (int r = 0; r < 4; r++) acc[mi][ni][r] = 0.f;

    issue_chunk(0, 0);
    issue_chunk(1, 1);

    for (int kc = 0; kc < 8; kc++) {
        if (kc == 7) { CP_WAIT(0); } else { CP_WAIT(1); }
        __syncthreads();
        if (kc + 2 < 8) issue_chunk(kc + 2, (kc + 2) % 3);

        const uint32_t base = sbase + (kc % 3) * IBUF;
#pragma unroll
        for (int kk = 0; kk < 4; kk++) {
            uint32_t ah[2][4], al[2][4], b[4][2];
            const uint32_t akoff = kk * 32 + (lane >> 4) * 16;
            const uint32_t bkoff = kk * 32 + ((lane >> 3) & 1) * 16;
#pragma unroll
            for (int mi = 0; mi < 2; mi++) {
                uint32_t ar = (warp_m * 32 + mi * 16 + (lane & 15)) * IROW + akoff;
                ldsm_x4(ah[mi], base + 0 * IMAT + ar);
                ldsm_x4(al[mi], base + 1 * IMAT + ar);
            }
#pragma unroll
            for (int ni = 0; ni < 4; ni++) {
                uint32_t br = (warp_n * 32 + ni * 8 + (lane & 7)) * IROW + bkoff;
                ldsm_x2(b[ni], base + 2 * IMAT + br);    // Bh
            }
#pragma unroll
            for (int mi = 0; mi < 2; mi++)
#pragma unroll
                for (int ni = 0; ni < 4; ni++) {
                    mma_fp16(acc[mi][ni], ah[mi], b[ni]);   // Ah*Bh
                    mma_fp16(acc[mi][ni], al[mi], b[ni]);   // Al*Bh
                }
#pragma unroll
            for (int ni = 0; ni < 4; ni++) {
                uint32_t br = (warp_n * 32 + ni * 8 + (lane & 7)) * IROW + bkoff;
                ldsm_x2(b[ni], base + 3 * IMAT + br);    // Bl
            }
#pragma unroll
            for (int mi = 0; mi < 2; mi++)
#pragma unroll
                for (int ni = 0; ni < 4; ni++)
                    mma_fp16(acc[mi][ni], ah[mi], b[ni]);   // Ah*Bl
        }
    }

    // epilogue: store fp32 + fp16 copies
#pragma unroll
    for (int mi = 0; mi < 2; mi++)
#pragma unroll
        for (int half = 0; half < 2; half++) {
            const int r = rowA0 + warp_m * 32 + mi * 16 + (lane >> 2) + half * 8;
#pragma unroll
            for (int ni = 0; ni < 4; ni++) {
                const int c = rowB0 + warp_n * 32 + ni * 8 + (lane & 3) * 2;
                float2 v = make_float2(acc[mi][ni][half * 2], acc[mi][ni][half * 2 + 1]);
                *(float2*)&g_implicit[(size_t)r * DIMK + c] = v;
                __half2 h;
                h.x = __float2half_rn(v.x);
                h.y = __float2half_rn(v.y);
                *(__half2*)&g_implicit_h[(size_t)r * DIMK + c] = h;
            }
        }
}

// =====================================================================
// Kernel 1b: c_norm[c] = ||implicit[c]||^2
// =====================================================================
__global__ void cnorm_kernel() {
    int c = blockIdx.x * 8 + (threadIdx.x >> 5);
    int lane = threadIdx.x & 31;
    const float* p = g_implicit + (size_t)c * DIMK;
    float s = 0.f;
#pragma unroll
    for (int j = 0; j < DIMK / 32; j++) {
        float v = p[lane + j * 32];
        s = fmaf(v, v, s);
    }
#pragma unroll
    for (int o = 16; o; o >>= 1) s += __shfl_xor_sync(0xffffffffu, s, o);
    if (lane == 0) g_cnorm[c] = s;
}

// =====================================================================
// Kernel 2: fp16 HMMA score GEMM + candidate collection.
// R13 CHAMPION — byte-for-byte unchanged (582us, best measured).
// =====================================================================
#define NBUF  3
#define BBUF  18432
#define SM_CN 0                       // 8192 floats = 32768 B
#define SM_A  32768                   // 128 rows x 1040 B = 133120 B
#define SM_B  (32768 + 133120)        // 165888
#define SM_TOTAL (SM_B + NBUF * BBUF) // 221184 B
#define AROW 1040
#define BROW 144

__global__ __launch_bounds__(512, 1)
void mma_argmin_kernel(const float* __restrict__ X) {
    extern __shared__ char smem[];
    const uint32_t sbase = smem_to_u32(smem);
    const int tid = threadIdx.x, lane = tid & 31, wid = tid >> 5;
    const int warp_m = wid & 3, warp_n = wid >> 2;
    const int row0 = blockIdx.x * 128;

    // B loader geometry: 4 threads/row, 32B each
    const int brow = tid >> 2;
    const int bcol = (tid & 3) * 32;

    // prologue: issue chunks 0 and 1 (fly during cnorm/A-convert)
    {
        const char* g0 = (const char*)g_implicit_h + ((size_t)brow * DIMK) * 2 + bcol;
        uint32_t d0 = sbase + SM_B + brow * BROW + bcol;
        CP_ASYNC16(d0, g0);
        CP_ASYNC16(d0 + 16, g0 + 16);
        CP_COMMIT();
        const char* g1 = (const char*)g_implicit_h + ((size_t)brow * DIMK + 64) * 2 + bcol;
        uint32_t d1 = sbase + SM_B + BBUF + brow * BROW + bcol;
        CP_ASYNC16(d1, g1);
        CP_ASYNC16(d1 + 16, g1 + 16);
        CP_COMMIT();
    }

    // cnorm -> SMEM (2048 float4, 512 threads x 4)
#pragma unroll
    for (int j = 0; j < 4; j++)
        ((float4*)smem)[tid + j * 512] = ((const float4*)g_cnorm)[tid + j * 512];

    // A-tile: convert 128 token rows fp32 -> fp16 into SMEM (4 thr/row)
    {
        const int r = tid >> 2, q = tid & 3;
        const float4* xr = (const float4*)(X + (size_t)(row0 + r) * DIMK) + q * 32;
        char* arow = smem + SM_A + r * AROW + q * 256;
#pragma unroll
        for (int j = 0; j < 16; j++) {
            float4 v0 = xr[2 * j], v1 = xr[2 * j + 1];
            __half2 h0, h1, h2, h3;
            h0.x = __float2half_rn(v0.x); h0.y = __float2half_rn(v0.y);
            h1.x = __float2half_rn(v0.z); h1.y = __float2half_rn(v0.w);
            h2.x = __float2half_rn(v1.x); h2.y = __float2half_rn(v1.y);
            h3.x = __float2half_rn(v1.z); h3.y = __float2half_rn(v1.w);
            uint4 pk;
            pk.x = *(uint32_t*)&h0; pk.y = *(uint32_t*)&h1;
            pk.z = *(uint32_t*)&h2; pk.w = *(uint32_t*)&h3;
            *(uint4*)(arow + j * 16) = pk;
        }
    }

    float acc[2][4][4];
#pragma unroll
    for (int mi = 0; mi < 2; mi++)
#pragma unroll
        for (int ni = 0; ni < 4; ni++)
#pragma unroll
            for (int r = 0; r < 4; r++) acc[mi][ni][r] = 0.f;

    float R[4]; int cnt[4];
#pragma unroll
    for (int s = 0; s < 4; s++) { R[s] = 3.4e38f; cnt[s] = 0; }

    int buf = 0;           // buffer holding chunk `it`
    for (int it = 0; it < 512; it++) {
        // groups retire in commit order: <=1 outstanding => chunk `it` landed
        if (it == 511) { CP_WAIT(0); } else { CP_WAIT(1); }
        __syncthreads();   // all warps done with buf[(it+2)%3]'s previous chunk

        if (it + 2 < 512) {  // prefetch chunk it+2: two iterations of slack
            const int nc = it + 2;
            const int nct = nc >> 3, nkc = nc & 7;
            const char* g = (const char*)g_implicit_h
                + ((size_t)(nct * 128 + brow) * DIMK + nkc * 64) * 2 + bcol;
            int nbuf = buf + 2; if (nbuf >= NBUF) nbuf -= NBUF;
            uint32_t d = sbase + SM_B + nbuf * BBUF + brow * BROW + bcol;
            CP_ASYNC16(d, g);
            CP_ASYNC16(d + 16, g + 16);
            CP_COMMIT();
        }

        const uint32_t b0 = sbase + SM_B + buf * BBUF;
        const int kc = it & 7;
#pragma unroll
        for (int kk = 0; kk < 4; kk++) {
            uint32_t a[2][4], b[4][2];
#pragma unroll
            for (int mi = 0; mi < 2; mi++) {
                uint32_t addr = sbase + SM_A
                    + (warp_m * 32 + mi * 16 + (lane & 15)) * AROW
                    + (kc * 64 + kk * 16 + (lane >> 4) * 8) * 2;
                ldsm_x4(a[mi], addr);
            }
#pragma unroll
            for (int ni = 0; ni < 4; ni++) {
                uint32_t addr = b0 + (warp_n * 32 + ni * 8 + (lane & 7)) * BROW
                    + (kk * 16 + ((lane >> 3) & 1) * 8) * 2;
                ldsm_x2(b[ni], addr);
            }
#pragma unroll
            for (int mi = 0; mi < 2; mi++)
#pragma unroll
                for (int ni = 0; ni < 4; ni++)
                    mma_fp16(acc[mi][ni], a[mi], b[ni]);
        }

        if (kc == 7) {
            const int ct = it >> 3;
#pragma unroll
            for (int mi = 0; mi < 2; mi++) {
#pragma unroll
                for (int half = 0; half < 2; half++) {
                    const int slot = mi * 2 + half;
                    float sv[8]; int cv[8];
#pragma unroll
                    for (int ni = 0; ni < 4; ni++) {
#pragma unroll
                        for (int rr = 0; rr < 2; rr++) {
                            int c = ct * 128 + warp_n * 32 + ni * 8 + (lane & 3) * 2 + rr;
                            float cn = *(const float*)(smem + 4 * c);
                            float s = fmaf(-2.f, acc[mi][ni][half * 2 + rr], cn);
                            sv[ni * 2 + rr] = s; cv[ni * 2 + rr] = c;
                            acc[mi][ni][half * 2 + rr] = 0.f;
                        }
                    }
                    float t = sv[0];
#pragma unroll
                    for (int j = 1; j < 8; j++) t = fminf(t, sv[j]);
                    t = fminf(t, __shfl_xor_sync(0xffffffffu, t, 1));
                    t = fminf(t, __shfl_xor_sync(0xffffffffu, t, 2));
                    R[slot] = fminf(R[slot], t);
                    const float thr = R[slot] + MARGIN;
                    if (t < thr) {
                        const int tok = row0 + warp_m * 32 + mi * 16 + (lane >> 2) + half * 8;
                        int* seg_base = g_cand + (size_t)tok * (NSEG * SEGCAP)
                                        + (warp_n * 4 + (lane & 3)) * SEGCAP;
#pragma unroll
                        for (int j = 0; j < 8; j++) {
                            if (sv[j] < thr) {
                                if (cnt[slot] < SEGCAP) seg_base[cnt[slot]] = cv[j];
                                cnt[slot]++;
                            }
                        }
                    }
                }
            }
        }
        buf++; if (buf == NBUF) buf = 0;
    }

#pragma unroll
    for (int mi = 0; mi < 2; mi++)
#pragma unroll
        for (int half = 0; half < 2; half++) {
            const int slot = mi * 2 + half;
            const int tok = row0 + warp_m * 32 + mi * 16 + (lane >> 2) + half * 8;
            const int seg = warp_n * 4 + (lane & 3);
            g_candcnt[(size_t)tok * NSEG + seg] = cnt[slot];
        }
}

// =====================================================================
// Kernel 2b: exact fp32 rescore, 4 WARPS PER TOKEN (quartered serial
// chain). Each warp owns 4 of 16 segments; overflow -> quarter of the
// codebook. SMEM merge with index tie-break; fused gather + partial.
// grid NTOK/2, 256 threads (2 tokens x 4 warps).
// =====================================================================
__global__ __launch_bounds__(256)
void rescue_kernel(const float* __restrict__ X, float* __restrict__ out,
                   int write_idx) {
    __shared__ float sbv[8];
    __shared__ int   sbi[8];
    __shared__ int   sovf[8];
    const int w = threadIdx.x >> 5, lane = threadIdx.x & 31;
    const int pair = w >> 2, quad = w & 3;
    const int t = blockIdx.x * 2 + pair;

    const float4* xr = (const float4*)(X + (size_t)t * DIMK) + lane * 4;
    const float4 x0 = xr[0], x1 = xr[1], x2 = xr[2], x3 = xr[3];

    int cnts[4]; bool myovf = false;
#pragma unroll
    for (int s = 0; s < 4; s++) {
        int c = g_candcnt[(size_t)t * NSEG + quad * 4 + s];
        cnts[s] = c;
        if (c > SEGCAP) myovf = true;
    }
    if (lane == 0) sovf[w] = myovf ? 1 : 0;
    __syncthreads();
    const bool ovf = (sovf[pair * 4] | sovf[pair * 4 + 1]
                    | sovf[pair * 4 + 2] | sovf[pair * 4 + 3]) != 0;

    float bv = 3.4e38f; int bi = 0x7fffffff;

    auto score = [&](int c) {
        const float4* cr = (const float4*)(g_implicit + (size_t)c * DIMK) + lane * 4;
        float4 c0 = cr[0], c1 = cr[1], c2 = cr[2], c3 = cr[3];
        float acc = 0.f;
        acc = fmaf(x0.x, c0.x, acc); acc = fmaf(x0.y, c0.y, acc);
        acc = fmaf(x0.z, c0.z, acc); acc = fmaf(x0.w, c0.w, acc);
        acc = fmaf(x1.x, c1.x, acc); acc = fmaf(x1.y, c1.y, acc);
        acc = fmaf(x1.z, c1.z, acc); acc = fmaf(x1.w, c1.w, acc);
        acc = fmaf(x2.x, c2.x, acc); acc = fmaf(x2.y, c2.y, acc);
        acc = fmaf(x2.z, c2.z, acc); acc = fmaf(x2.w, c2.w, acc);
        acc = fmaf(x3.x, c3.x, acc); acc = fmaf(x3.y, c3.y, acc);
        acc = fmaf(x3.z, c3.z, acc); acc = fmaf(x3.w, c3.w, acc);
#pragma unroll
        for (int o = 16; o; o >>= 1) acc += __shfl_xor_sync(0xffffffffu, acc, o);
        float s = fmaf(-2.0f, acc, __ldg(&g_cnorm[c]));
        if (s < bv || (s == bv && c < bi)) { bv = s; bi = c; }
    };

    if (ovf) {
        for (int c = quad * (NCODE / 4); c < (quad + 1) * (NCODE / 4); c++) score(c);
    } else {
#pragma unroll 1
        for (int s = 0; s < 4; s++) {
            const int* seg = g_cand + (size_t)t * (NSEG * SEGCAP)
                             + (quad * 4 + s) * SEGCAP;
            for (int j = 0; j < cnts[s]; j++) score(seg[j]);
        }
    }

    if (lane == 0) { sbv[w] = bv; sbi[w] = bi; }
    __syncthreads();

    if (quad == 0) {
#pragma unroll
        for (int o = 1; o < 4; o++) {
            float bv2 = sbv[w + o]; int bi2 = sbi[w + o];
            if (bv2 < bv || (bv2 == bv && bi2 < bi)) { bv = bv2; bi = bi2; }
        }

        const float4* qr = (const float4*)(g_implicit + (size_t)bi * DIMK) + lane * 4;
        const float4 q0 = qr[0], q1 = qr[1], q2 = qr[2], q3 = qr[3];
        float4* orow = (float4*)out + (size_t)t * (DIMK / 4) + lane * 4;
        orow[0] = q0; orow[1] = q1; orow[2] = q2; orow[3] = q3;

        float s =
            (x0.x - q0.x) * (x0.x - q0.x) + (x0.y - q0.y) * (x0.y - q0.y) +
            (x0.z - q0.z) * (x0.z - q0.z) + (x0.w - q0.w) * (x0.w - q0.w) +
            (x1.x - q1.x) * (x1.x - q1.x) + (x1.y - q1.y) * (x1.y - q1.y) +
            (x1.z - q1.z) * (x1.z - q1.z) + (x1.w - q1.w) * (x1.w - q1.w) +
            (x2.x - q2.x) * (x2.x - q2.x) + (x2.y - q2.y) * (x2.y - q2.y) +
            (x2.z - q2.z) * (x2.z - q2.z) + (x2.w - q2.w) * (x2.w - q2.w) +
            (x3.x - q3.x) * (x3.x - q3.x) + (x3.y - q3.y) * (x3.y - q3.y) +
            (x3.z - q3.z) * (x3.z - q3.z) + (x3.w - q3.w) * (x3.w - q3.w);
#pragma unroll
        for (int o = 16; o; o >>= 1) s += __shfl_xor_sync(0xffffffffu, s, o);
        if (lane == 0) {
            g_partial[t] = s;
            if (write_idx) out[(size_t)QELEMS + t] = (float)bi;
        }
    }
}

// =====================================================================
// Kernel 4: deterministic loss reduction (fp64 accumulate).
// =====================================================================
__global__ void loss_kernel(float* __restrict__ out_loss) {
    __shared__ double sh[256];
    double s = 0.0;
    for (int i = threadIdx.x; i < NTOK; i += 256) s += (double)g_partial[i];
    sh[threadIdx.x] = s;
    __syncthreads();
    for (int o = 128; o; o >>= 1) {
        if (threadIdx.x < o) sh[threadIdx.x] += sh[threadIdx.x + o];
        __syncthreads();
    }
    if (threadIdx.x == 0)
        *out_loss = (float)(1.25 * sh[0] / (double)QELEMS);
}

// =====================================================================
extern "C" void kernel_launch(void* const* d_in, const int* in_sizes, int n_in,
                              void* d_out, int out_size) {
    const float* x = nullptr; const float* cb = nullptr; const float* W = nullptr;
    for (int i = 0; i < n_in; i++) {
        if (in_sizes[i] == NTOK * DIMK)       x  = (const float*)d_in[i];
        else if (in_sizes[i] == NCODE * DIMK) cb = (const float*)d_in[i];
        else if (in_sizes[i] == DIMK * DIMK)  W  = (const float*)d_in[i];
    }
    float* out = (float*)d_out;

    split_kernel<<<(CB_F4 + W_F4 + 255) / 256, 256>>>(cb, W);

    cudaFuncSetAttribute(implicit_split_kernel,
                         cudaFuncAttributeMaxDynamicSharedMemorySize, ISM_TOTAL);
    implicit_split_kernel<<<dim3(NCODE / 128, DIMK / 128), 512, ISM_TOTAL>>>();

    cnorm_kernel<<<NCODE / 8, 256>>>();

    cudaFuncSetAttribute(mma_argmin_kernel,
                         cudaFuncAttributeMaxDynamicSharedMemorySize, SM_TOTAL);
    mma_argmin_kernel<<<NTOK / 128, 512, SM_TOTAL>>>(x);

    const int write_idx = (out_size >= QELEMS + NTOK) ? 1 : 0;
    rescue_kernel<<<NTOK / 2, 256>>>(x, out, write_idx);

    if (out_size >= QELEMS + NTOK + 1)
        loss_kernel<<<1, 256>>>(out + (size_t)QELEMS + NTOK);
}

// round 17
// speedup vs baseline: 1.1043x; 1.0423x over previous
#include <cuda_runtime.h>
#include <cuda_bf16.h>
#include <cuda_fp16.h>
#include <cstdint>

// Problem constants
#define DIMK   512
#define NCODE  8192
#define NTOK   16384           // B*N = 4*4096
#define QELEMS (NTOK * DIMK)   // 8388608

#define MARGIN   0.09f          // worst-case fp16 score error ~0.047; 2x safety
#define SEGCAP   16
#define NSEG     16             // per token: 16 segments x 16 entries

// ---------------- scratch (no allocations allowed) ----------------
__device__ float   g_implicit[(size_t)NCODE * DIMK];    // 16 MB fp32 (exact)
__device__ __half  g_implicit_h[(size_t)NCODE * DIMK];  // 8 MB fp16 (for HMMA)
__device__ __half  g_cbh[(size_t)NCODE * DIMK];         // codebook hi
__device__ __half  g_cbl[(size_t)NCODE * DIMK];         // codebook lo
__device__ __half  g_wh[(size_t)DIMK * DIMK];           // W hi
__device__ __half  g_wl[(size_t)DIMK * DIMK];           // W lo
__device__ float   g_cnorm[NCODE];
__device__ float   g_partial[NTOK];
__device__ int     g_cand[(size_t)NTOK * NSEG * SEGCAP];  // 16 MB
__device__ int     g_candcnt[(size_t)NTOK * NSEG];        // 1 MB

// ===================== helpers =====================
__device__ __forceinline__ uint32_t smem_to_u32(const void* p) {
    uint32_t a;
    asm("{ .reg .u64 t; cvta.to.shared.u64 t, %1; cvt.u32.u64 %0, t; }" : "=r"(a) : "l"(p));
    return a;
}
// L2-direct bulk copy (validated R9: .ca's L1 fill thrashes the small L1 slice)
#define CP_ASYNC16(dst, src) \
    asm volatile("cp.async.cg.shared.global [%0], [%1], 16;" :: "r"(dst), "l"(src))
#define CP_COMMIT() asm volatile("cp.async.commit_group;")
#define CP_WAIT(n)  asm volatile("cp.async.wait_group %0;" :: "n"(n))

__device__ __forceinline__ void ldsm_x4(uint32_t r[4], uint32_t addr) {
    asm volatile("ldmatrix.sync.aligned.m8n8.x4.shared.b16 {%0,%1,%2,%3}, [%4];"
                 : "=r"(r[0]), "=r"(r[1]), "=r"(r[2]), "=r"(r[3]) : "r"(addr));
}
__device__ __forceinline__ void ldsm_x2(uint32_t r[2], uint32_t addr) {
    asm volatile("ldmatrix.sync.aligned.m8n8.x2.shared.b16 {%0,%1}, [%2];"
                 : "=r"(r[0]), "=r"(r[1]) : "r"(addr));
}
__device__ __forceinline__ void mma_fp16(float d[4], const uint32_t a[4], const uint32_t b[2]) {
    asm volatile("mma.sync.aligned.m16n8k16.row.col.f32.f16.f16.f32 "
                 "{%0,%1,%2,%3}, {%4,%5,%6,%7}, {%8,%9}, {%0,%1,%2,%3};"
                 : "+f"(d[0]), "+f"(d[1]), "+f"(d[2]), "+f"(d[3])
                 : "r"(a[0]), "r"(a[1]), "r"(a[2]), "r"(a[3]), "r"(b[0]), "r"(b[1]));
}

// =====================================================================
// Kernel 0: hi/lo fp16 split of codebook and W.
// =====================================================================
#define CB_F4 ((NCODE * DIMK) / 4)   // 1048576
#define W_F4  ((DIMK * DIMK) / 4)    // 65536
__global__ __launch_bounds__(256)
void split_kernel(const float* __restrict__ CB, const float* __restrict__ W) {
    const int idx = blockIdx.x * 256 + threadIdx.x;
    const float4* src;
    __half2 *dh, *dl;
    int i = idx;
    if (idx < CB_F4) {
        src = (const float4*)CB; dh = (__half2*)g_cbh; dl = (__half2*)g_cbl;
    } else {
        i = idx - CB_F4;
        if (i >= W_F4) return;
        src = (const float4*)W; dh = (__half2*)g_wh; dl = (__half2*)g_wl;
    }
    float4 v = src[i];
    __half hx = __float2half_rn(v.x), hy = __float2half_rn(v.y);
    __half hz = __float2half_rn(v.z), hw = __float2half_rn(v.w);
    __half lx = __float2half_rn(v.x - __half2float(hx));
    __half ly = __float2half_rn(v.y - __half2float(hy));
    __half lz = __float2half_rn(v.z - __half2float(hz));
    __half lw = __float2half_rn(v.w - __half2float(hw));
    dh[i * 2]     = __halves2half2(hx, hy);
    dh[i * 2 + 1] = __halves2half2(hz, hw);
    dl[i * 2]     = __halves2half2(lx, ly);
    dl[i * 2 + 1] = __halves2half2(lz, lw);
}

// =====================================================================
// Kernel 1: implicit[c,d] via split-fp16 HMMA.
// R17: ONE-WAVE grid. Tile 256 codes x 128 dcols, grid (32,4) = 128
// CTAs (one wave on 148 SMs), 512 threads = 16 warps as 8(M) x 2(N),
// warp tile 32x64. K in 8 chunks of 64, 2-deep cp.async ring.
// D = Ah*Bh + Al*Bh + Ah*Bl (fp32 accum; Al*Bl dropped ~2^-22 rel).
// SMEM/buffer: Ah,Al 256x144 + Bh,Bl 128x144 = 110592; x2 = 221184.
// =====================================================================
#define IROW  144
#define IA_SZ (256 * IROW)            // 36864
#define IB_SZ (128 * IROW)            // 18432
#define I_AH  0
#define I_AL  IA_SZ
#define I_BH  (2 * IA_SZ)
#define I_BL  (2 * IA_SZ + IB_SZ)
#define IBUF  (2 * IA_SZ + 2 * IB_SZ) // 110592
#define ISM_TOTAL (2 * IBUF)          // 221184

__global__ __launch_bounds__(512, 1)
void implicit_split_kernel() {
    extern __shared__ char smem[];
    const uint32_t sbase = smem_to_u32(smem);
    const int tid = threadIdx.x, lane = tid & 31, wid = tid >> 5;
    const int warp_m = wid & 7, warp_n = wid >> 3;   // 8 x 2
    const int rowA0 = blockIdx.x * 256;   // codes
    const int rowB0 = blockIdx.y * 128;   // d-cols

    // loader split: A rows 2 thr/row (64B each), B rows 4 thr/row (32B each)
    const int ar = tid >> 1, ahalf = (tid & 1) * 64;
    const int br = tid >> 2, bq = (tid & 3) * 32;

    auto issue_chunk = [&](int kc, int bu) {
        const uint32_t base = sbase + bu * IBUF;
        {   // Ah / Al : 64 B per thread each
            const size_t off = ((size_t)(rowA0 + ar) * DIMK + kc * 64) * 2 + ahalf;
            const uint32_t d = base + ar * IROW + ahalf;
#pragma unroll
            for (int i = 0; i < 4; i++) {
                CP_ASYNC16(d + I_AH + i * 16, (const char*)g_cbh + off + i * 16);
                CP_ASYNC16(d + I_AL + i * 16, (const char*)g_cbl + off + i * 16);
            }
        }
        {   // Bh / Bl : 32 B per thread each
            const size_t off = ((size_t)(rowB0 + br) * DIMK + kc * 64) * 2 + bq;
            const uint32_t d = base + br * IROW + bq;
#pragma unroll
            for (int i = 0; i < 2; i++) {
                CP_ASYNC16(d + I_BH + i * 16, (const char*)g_wh + off + i * 16);
                CP_ASYNC16(d + I_BL + i * 16, (const char*)g_wl + off + i * 16);
            }
        }
        CP_COMMIT();
    };

    float acc[2][8][4];
#pragma unroll
    for (int mi = 0; mi < 2; mi++)
#pragma unroll
        for (int ni = 0; ni < 8; ni++)
#pragma unroll
            for (int r = 0; r < 4; r++) acc[mi][ni][r] = 0.f;

    issue_chunk(0, 0);

    for (int kc = 0; kc < 8; kc++) {
        CP_WAIT(0);
        __syncthreads();
        if (kc + 1 < 8) issue_chunk(kc + 1, (kc + 1) & 1);

        const uint32_t base = sbase + (kc & 1) * IBUF;
#pragma unroll
        for (int kk = 0; kk < 4; kk++) {
            uint32_t ah[2][4], al[2][4], b[8][2];
            const uint32_t akoff = kk * 32 + (lane >> 4) * 16;
            const uint32_t bkoff = kk * 32 + ((lane >> 3) & 1) * 16;
#pragma unroll
            for (int mi = 0; mi < 2; mi++) {
                uint32_t arow = (warp_m * 32 + mi * 16 + (lane & 15)) * IROW + akoff;
                ldsm_x4(ah[mi], base + I_AH + arow);
                ldsm_x4(al[mi], base + I_AL + arow);
            }
#pragma unroll
            for (int ni = 0; ni < 8; ni++) {
                uint32_t brow = (warp_n * 64 + ni * 8 + (lane & 7)) * IROW + bkoff;
                ldsm_x2(b[ni], base + I_BH + brow);   // Bh
            }
#pragma unroll
            for (int mi = 0; mi < 2; mi++)
#pragma unroll
                for (int ni = 0; ni < 8; ni++) {
                    mma_fp16(acc[mi][ni], ah[mi], b[ni]);   // Ah*Bh
                    mma_fp16(acc[mi][ni], al[mi], b[ni]);   // Al*Bh
                }
#pragma unroll
            for (int ni = 0; ni < 8; ni++) {
                uint32_t brow = (warp_n * 64 + ni * 8 + (lane & 7)) * IROW + bkoff;
                ldsm_x2(b[ni], base + I_BL + brow);   // Bl
            }
#pragma unroll
            for (int mi = 0; mi < 2; mi++)
#pragma unroll
                for (int ni = 0; ni < 8; ni++)
                    mma_fp16(acc[mi][ni], ah[mi], b[ni]);   // Ah*Bl
        }
    }

    // epilogue: store fp32 + fp16 copies
#pragma unroll
    for (int mi = 0; mi < 2; mi++)
#pragma unroll
        for (int half = 0; half < 2; half++) {
            const int r = rowA0 + warp_m * 32 + mi * 16 + (lane >> 2) + half * 8;
#pragma unroll
            for (int ni = 0; ni < 8; ni++) {
                const int c = rowB0 + warp_n * 64 + ni * 8 + (lane & 3) * 2;
                float2 v = make_float2(acc[mi][ni][half * 2], acc[mi][ni][half * 2 + 1]);
                *(float2*)&g_implicit[(size_t)r * DIMK + c] = v;
                __half2 h;
                h.x = __float2half_rn(v.x);
                h.y = __float2half_rn(v.y);
                *(__half2*)&g_implicit_h[(size_t)r * DIMK + c] = h;
            }
        }
}

// =====================================================================
// Kernel 1b: c_norm[c] = ||implicit[c]||^2
// =====================================================================
__global__ void cnorm_kernel() {
    int c = blockIdx.x * 8 + (threadIdx.x >> 5);
    int lane = threadIdx.x & 31;
    const float* p = g_implicit + (size_t)c * DIMK;
    float s = 0.f;
#pragma unroll
    for (int j = 0; j < DIMK / 32; j++) {
        float v = p[lane + j * 32];
        s = fmaf(v, v, s);
    }
#pragma unroll
    for (int o = 16; o; o >>= 1) s += __shfl_xor_sync(0xffffffffu, s, o);
    if (lane == 0) g_cnorm[c] = s;
}

// =====================================================================
// Kernel 2: fp16 HMMA score GEMM + candidate collection.
// R13 CHAMPION — byte-for-byte unchanged (582us, best measured).
// =====================================================================
#define NBUF  3
#define BBUF  18432
#define SM_CN 0                       // 8192 floats = 32768 B
#define SM_A  32768                   // 128 rows x 1040 B = 133120 B
#define SM_B  (32768 + 133120)        // 165888
#define SM_TOTAL (SM_B + NBUF * BBUF) // 221184 B
#define AROW 1040
#define BROW 144

__global__ __launch_bounds__(512, 1)
void mma_argmin_kernel(const float* __restrict__ X) {
    extern __shared__ char smem[];
    const uint32_t sbase = smem_to_u32(smem);
    const int tid = threadIdx.x, lane = tid & 31, wid = tid >> 5;
    const int warp_m = wid & 3, warp_n = wid >> 2;
    const int row0 = blockIdx.x * 128;

    // B loader geometry: 4 threads/row, 32B each
    const int brow = tid >> 2;
    const int bcol = (tid & 3) * 32;

    // prologue: issue chunks 0 and 1 (fly during cnorm/A-convert)
    {
        const char* g0 = (const char*)g_implicit_h + ((size_t)brow * DIMK) * 2 + bcol;
        uint32_t d0 = sbase + SM_B + brow * BROW + bcol;
        CP_ASYNC16(d0, g0);
        CP_ASYNC16(d0 + 16, g0 + 16);
        CP_COMMIT();
        const char* g1 = (const char*)g_implicit_h + ((size_t)brow * DIMK + 64) * 2 + bcol;
        uint32_t d1 = sbase + SM_B + BBUF + brow * BROW + bcol;
        CP_ASYNC16(d1, g1);
        CP_ASYNC16(d1 + 16, g1 + 16);
        CP_COMMIT();
    }

    // cnorm -> SMEM (2048 float4, 512 threads x 4)
#pragma unroll
    for (int j = 0; j < 4; j++)
        ((float4*)smem)[tid + j * 512] = ((const float4*)g_cnorm)[tid + j * 512];

    // A-tile: convert 128 token rows fp32 -> fp16 into SMEM (4 thr/row)
    {
        const int r = tid >> 2, q = tid & 3;
        const float4* xr = (const float4*)(X + (size_t)(row0 + r) * DIMK) + q * 32;
        char* arow = smem + SM_A + r * AROW + q * 256;
#pragma unroll
        for (int j = 0; j < 16; j++) {
            float4 v0 = xr[2 * j], v1 = xr[2 * j + 1];
            __half2 h0, h1, h2, h3;
            h0.x = __float2half_rn(v0.x); h0.y = __float2half_rn(v0.y);
            h1.x = __float2half_rn(v0.z); h1.y = __float2half_rn(v0.w);
            h2.x = __float2half_rn(v1.x); h2.y = __float2half_rn(v1.y);
            h3.x = __float2half_rn(v1.z); h3.y = __float2half_rn(v1.w);
            uint4 pk;
            pk.x = *(uint32_t*)&h0; pk.y = *(uint32_t*)&h1;
            pk.z = *(uint32_t*)&h2; pk.w = *(uint32_t*)&h3;
            *(uint4*)(arow + j * 16) = pk;
        }
    }

    float acc[2][4][4];
#pragma unroll
    for (int mi = 0; mi < 2; mi++)
#pragma unroll
        for (int ni = 0; ni < 4; ni++)
#pragma unroll
            for (int r = 0; r < 4; r++) acc[mi][ni][r] = 0.f;

    float R[4]; int cnt[4];
#pragma unroll
    for (int s = 0; s < 4; s++) { R[s] = 3.4e38f; cnt[s] = 0; }

    int buf = 0;           // buffer holding chunk `it`
    for (int it = 0; it < 512; it++) {
        // groups retire in commit order: <=1 outstanding => chunk `it` landed
        if (it == 511) { CP_WAIT(0); } else { CP_WAIT(1); }
        __syncthreads();   // all warps done with buf[(it+2)%3]'s previous chunk

        if (it + 2 < 512) {  // prefetch chunk it+2: two iterations of slack
            const int nc = it + 2;
            const int nct = nc >> 3, nkc = nc & 7;
            const char* g = (const char*)g_implicit_h
                + ((size_t)(nct * 128 + brow) * DIMK + nkc * 64) * 2 + bcol;
            int nbuf = buf + 2; if (nbuf >= NBUF) nbuf -= NBUF;
            uint32_t d = sbase + SM_B + nbuf * BBUF + brow * BROW + bcol;
            CP_ASYNC16(d, g);
            CP_ASYNC16(d + 16, g + 16);
            CP_COMMIT();
        }

        const uint32_t b0 = sbase + SM_B + buf * BBUF;
        const int kc = it & 7;
#pragma unroll
        for (int kk = 0; kk < 4; kk++) {
            uint32_t a[2][4], b[4][2];
#pragma unroll
            for (int mi = 0; mi < 2; mi++) {
                uint32_t addr = sbase + SM_A
                    + (warp_m * 32 + mi * 16 + (lane & 15)) * AROW
                    + (kc * 64 + kk * 16 + (lane >> 4) * 8) * 2;
                ldsm_x4(a[mi], addr);
            }
#pragma unroll
            for (int ni = 0; ni < 4; ni++) {
                uint32_t addr = b0 + (warp_n * 32 + ni * 8 + (lane & 7)) * BROW
                    + (kk * 16 + ((lane >> 3) & 1) * 8) * 2;
                ldsm_x2(b[ni], addr);
            }
#pragma unroll
            for (int mi = 0; mi < 2; mi++)
#pragma unroll
                for (int ni = 0; ni < 4; ni++)
                    mma_fp16(acc[mi][ni], a[mi], b[ni]);
        }

        if (kc == 7) {
            const int ct = it >> 3;
#pragma unroll
            for (int mi = 0; mi < 2; mi++) {
#pragma unroll
                for (int half = 0; half < 2; half++) {
                    const int slot = mi * 2 + half;
                    float sv[8]; int cv[8];
#pragma unroll
                    for (int ni = 0; ni < 4; ni++) {
#pragma unroll
                        for (int rr = 0; rr < 2; rr++) {
                            int c = ct * 128 + warp_n * 32 + ni * 8 + (lane & 3) * 2 + rr;
                            float cn = *(const float*)(smem + 4 * c);
                            float s = fmaf(-2.f, acc[mi][ni][half * 2 + rr], cn);
                            sv[ni * 2 + rr] = s; cv[ni * 2 + rr] = c;
                            acc[mi][ni][half * 2 + rr] = 0.f;
                        }
                    }
                    float t = sv[0];
#pragma unroll
                    for (int j = 1; j < 8; j++) t = fminf(t, sv[j]);
                    t = fminf(t, __shfl_xor_sync(0xffffffffu, t, 1));
                    t = fminf(t, __shfl_xor_sync(0xffffffffu, t, 2));
                    R[slot] = fminf(R[slot], t);
                    const float thr = R[slot] + MARGIN;
                    if (t < thr) {
                        const int tok = row0 + warp_m * 32 + mi * 16 + (lane >> 2) + half * 8;
                        int* seg_base = g_cand + (size_t)tok * (NSEG * SEGCAP)
                                        + (warp_n * 4 + (lane & 3)) * SEGCAP;
#pragma unroll
                        for (int j = 0; j < 8; j++) {
                            if (sv[j] < thr) {
                                if (cnt[slot] < SEGCAP) seg_base[cnt[slot]] = cv[j];
                                cnt[slot]++;
                            }
                        }
                    }
                }
            }
        }
        buf++; if (buf == NBUF) buf = 0;
    }

#pragma unroll
    for (int mi = 0; mi < 2; mi++)
#pragma unroll
        for (int half = 0; half < 2; half++) {
            const int slot = mi * 2 + half;
            const int tok = row0 + warp_m * 32 + mi * 16 + (lane >> 2) + half * 8;
            const int seg = warp_n * 4 + (lane & 3);
            g_candcnt[(size_t)tok * NSEG + seg] = cnt[slot];
        }
}

// =====================================================================
// Kernel 2b: exact fp32 rescore, 2 warps/token (R13-proven, unchanged).
// =====================================================================
__global__ __launch_bounds__(256)
void rescue_kernel(const float* __restrict__ X, float* __restrict__ out,
                   int write_idx) {
    __shared__ float sbv[8];
    __shared__ int   sbi[8];
    __shared__ int   sovf[8];
    const int w = threadIdx.x >> 5, lane = threadIdx.x & 31;
    const int pair = w >> 1, half = w & 1;
    const int t = blockIdx.x * 4 + pair;

    const float4* xr = (const float4*)(X + (size_t)t * DIMK) + lane * 4;
    const float4 x0 = xr[0], x1 = xr[1], x2 = xr[2], x3 = xr[3];

    int cnts[8]; bool myovf = false;
#pragma unroll
    for (int s = 0; s < 8; s++) {
        int c = g_candcnt[(size_t)t * NSEG + half * 8 + s];
        cnts[s] = c;
        if (c > SEGCAP) myovf = true;
    }
    if (lane == 0) sovf[w] = myovf ? 1 : 0;
    __syncthreads();
    const bool ovf = (sovf[pair * 2] | sovf[pair * 2 + 1]) != 0;

    float bv = 3.4e38f; int bi = 0x7fffffff;

    auto score = [&](int c) {
        const float4* cr = (const float4*)(g_implicit + (size_t)c * DIMK) + lane * 4;
        float4 c0 = cr[0], c1 = cr[1], c2 = cr[2], c3 = cr[3];
        float acc = 0.f;
        acc = fmaf(x0.x, c0.x, acc); acc = fmaf(x0.y, c0.y, acc);
        acc = fmaf(x0.z, c0.z, acc); acc = fmaf(x0.w, c0.w, acc);
        acc = fmaf(x1.x, c1.x, acc); acc = fmaf(x1.y, c1.y, acc);
        acc = fmaf(x1.z, c1.z, acc); acc = fmaf(x1.w, c1.w, acc);
        acc = fmaf(x2.x, c2.x, acc); acc = fmaf(x2.y, c2.y, acc);
        acc = fmaf(x2.z, c2.z, acc); acc = fmaf(x2.w, c2.w, acc);
        acc = fmaf(x3.x, c3.x, acc); acc = fmaf(x3.y, c3.y, acc);
        acc = fmaf(x3.z, c3.z, acc); acc = fmaf(x3.w, c3.w, acc);
#pragma unroll
        for (int o = 16; o; o >>= 1) acc += __shfl_xor_sync(0xffffffffu, acc, o);
        float s = fmaf(-2.0f, acc, __ldg(&g_cnorm[c]));
        if (s < bv || (s == bv && c < bi)) { bv = s; bi = c; }
    };

    if (ovf) {
        for (int c = half * (NCODE / 2); c < (half + 1) * (NCODE / 2); c++) score(c);
    } else {
#pragma unroll 1
        for (int s = 0; s < 8; s++) {
            const int* seg = g_cand + (size_t)t * (NSEG * SEGCAP)
                             + (half * 8 + s) * SEGCAP;
            for (int j = 0; j < cnts[s]; j++) score(seg[j]);
        }
    }

    if (lane == 0) { sbv[w] = bv; sbi[w] = bi; }
    __syncthreads();

    if (half == 0) {
        float bv2 = sbv[w + 1]; int bi2 = sbi[w + 1];
        if (bv2 < bv || (bv2 == bv && bi2 < bi)) { bv = bv2; bi = bi2; }

        const float4* qr = (const float4*)(g_implicit + (size_t)bi * DIMK) + lane * 4;
        const float4 q0 = qr[0], q1 = qr[1], q2 = qr[2], q3 = qr[3];
        float4* orow = (float4*)out + (size_t)t * (DIMK / 4) + lane * 4;
        orow[0] = q0; orow[1] = q1; orow[2] = q2; orow[3] = q3;

        float s =
            (x0.x - q0.x) * (x0.x - q0.x) + (x0.y - q0.y) * (x0.y - q0.y) +
            (x0.z - q0.z) * (x0.z - q0.z) + (x0.w - q0.w) * (x0.w - q0.w) +
            (x1.x - q1.x) * (x1.x - q1.x) + (x1.y - q1.y) * (x1.y - q1.y) +
            (x1.z - q1.z) * (x1.z - q1.z) + (x1.w - q1.w) * (x1.w - q1.w) +
            (x2.x - q2.x) * (x2.x - q2.x) + (x2.y - q2.y) * (x2.y - q2.y) +
            (x2.z - q2.z) * (x2.z - q2.z) + (x2.w - q2.w) * (x2.w - q2.w) +
            (x3.x - q3.x) * (x3.x - q3.x) + (x3.y - q3.y) * (x3.y - q3.y) +
            (x3.z - q3.z) * (x3.z - q3.z) + (x3.w - q3.w) * (x3.w - q3.w);
#pragma unroll
        for (int o = 16; o; o >>= 1) s += __shfl_xor_sync(0xffffffffu, s, o);
        if (lane == 0) {
            g_partial[t] = s;
            if (write_idx) out[(size_t)QELEMS + t] = (float)bi;
        }
    }
}

// =====================================================================
// Kernel 4: deterministic loss reduction (fp64 accumulate).
// =====================================================================
__global__ void loss_kernel(float* __restrict__ out_loss) {
    __shared__ double sh[256];
    double s = 0.0;
    for (int i = threadIdx.x; i < NTOK; i += 256) s += (double)g_partial[i];
    sh[threadIdx.x] = s;
    __syncthreads();
    for (int o = 128; o; o >>= 1) {
        if (threadIdx.x < o) sh[threadIdx.x] += sh[threadIdx.x + o];
        __syncthreads();
    }
    if (threadIdx.x == 0)
        *out_loss = (float)(1.25 * sh[0] / (double)QELEMS);
}

// =====================================================================
extern "C" void kernel_launch(void* const* d_in, const int* in_sizes, int n_in,
                              void* d_out, int out_size) {
    const float* x = nullptr; const float* cb = nullptr; const float* W = nullptr;
    for (int i = 0; i < n_in; i++) {
        if (in_sizes[i] == NTOK * DIMK)       x  = (const float*)d_in[i];
        else if (in_sizes[i] == NCODE * DIMK) cb = (const float*)d_in[i];
        else if (in_sizes[i] == DIMK * DIMK)  W  = (const float*)d_in[i];
    }
    float* out = (float*)d_out;

    split_kernel<<<(CB_F4 + W_F4 + 255) / 256, 256>>>(cb, W);

    cudaFuncSetAttribute(implicit_split_kernel,
                         cudaFuncAttributeMaxDynamicSharedMemorySize, ISM_TOTAL);
    implicit_split_kernel<<<dim3(NCODE / 256, DIMK / 128), 512, ISM_TOTAL>>>();

    cnorm_kernel<<<NCODE / 8, 256>>>();

    cudaFuncSetAttribute(mma_argmin_kernel,
                         cudaFuncAttributeMaxDynamicSharedMemorySize, SM_TOTAL);
    mma_argmin_kernel<<<NTOK / 128, 512, SM_TOTAL>>>(x);

    const int write_idx = (out_size >= QELEMS + NTOK) ? 1 : 0;
    rescue_kernel<<<NTOK / 4, 256>>>(x, out, write_idx);

    if (out_size >= QELEMS + NTOK + 1)
        loss_kernel<<<1, 256>>>(out + (size_t)QELEMS + NTOK);
}